// round 1
// baseline (speedup 1.0000x reference)
#include <cuda_runtime.h>
#include <math_constants.h>

// Problem shape (fixed by the reference: N=32768, C=4096).
constexpr int NROWS = 32768;
constexpr int NCOLS = 4096;
constexpr int TPB   = 256;           // threads per row-block
constexpr int V4PT  = NCOLS / (TPB * 4);  // float4 loads per thread = 4

// Scratch: per-row log_p. __device__ global (no allocations allowed).
__device__ float g_logp[NROWS];
// Flag: 1 if target buffer is int64, 0 if int32.
__device__ int g_tgt_is64;

// ---------------------------------------------------------------------------
// Detect target dtype. target values are in [0, 4096), so if the buffer is
// int64 (little-endian), every odd 32-bit word is 0. If int32, odd words are
// random targets — probability all 16 checked are zero is (1/4096)^16 ~ 0.
// ---------------------------------------------------------------------------
__global__ void detect_tgt_kernel(const int* __restrict__ w) {
    int all0 = 1;
#pragma unroll
    for (int i = 1; i < 32; i += 2) all0 &= (w[i] == 0);
    g_tgt_is64 = all0;
}

// ---------------------------------------------------------------------------
// One block per row. log_z = M + log(sum_j w_j * exp(x_j - M)), M = max_j x_j.
// (Valid shift: log w <= 0 so true max of (log w + x) <= M; the argmax term
//  contributes w >= 1e-4, so no underflow of the sum.)
// ---------------------------------------------------------------------------
__global__ __launch_bounds__(TPB) void row_kernel(
        const float* __restrict__ logits,
        const float* __restrict__ factor,
        const void*  __restrict__ target) {
    const int    row  = blockIdx.x;
    const int    t    = threadIdx.x;
    const size_t base = (size_t)row * NCOLS;
    const float4* lg = reinterpret_cast<const float4*>(logits + base);
    const float4* fc = reinterpret_cast<const float4*>(factor + base);

    // Stage the whole row slice in registers. Streaming loads (touch-once).
    float xr[4 * V4PT], wr[4 * V4PT];
#pragma unroll
    for (int k = 0; k < V4PT; k++) {
        float4 v = __ldcs(lg + t + k * TPB);
        xr[4*k+0] = v.x; xr[4*k+1] = v.y; xr[4*k+2] = v.z; xr[4*k+3] = v.w;
    }
#pragma unroll
    for (int k = 0; k < V4PT; k++) {
        float4 v = __ldcs(fc + t + k * TPB);
        wr[4*k+0] = v.x; wr[4*k+1] = v.y; wr[4*k+2] = v.z; wr[4*k+3] = v.w;
    }

    // ---- pass 1 (registers): thread-local max, then block max ----
    float m = -CUDART_INF_F;
#pragma unroll
    for (int i = 0; i < 4 * V4PT; i++) m = fmaxf(m, xr[i]);

    __shared__ float sred[TPB / 32];
    const int warp = t >> 5, lane = t & 31;
#pragma unroll
    for (int o = 16; o > 0; o >>= 1) m = fmaxf(m, __shfl_xor_sync(0xffffffffu, m, o));
    if (lane == 0) sred[warp] = m;
    __syncthreads();
    if (warp == 0) {
        float v = sred[lane & (TPB / 32 - 1)];
#pragma unroll
        for (int o = (TPB / 64); o > 0; o >>= 1) v = fmaxf(v, __shfl_xor_sync(0xffffffffu, v, o));
        if (lane == 0) sred[0] = v;
    }
    __syncthreads();
    const float M = sred[0];
    __syncthreads();   // sred reused below

    // ---- pass 2 (registers): sum w * exp(x - M), then block sum ----
    float s = 0.f;
#pragma unroll
    for (int i = 0; i < 4 * V4PT; i++) s += wr[i] * __expf(xr[i] - M);

#pragma unroll
    for (int o = 16; o > 0; o >>= 1) s += __shfl_xor_sync(0xffffffffu, s, o);
    if (lane == 0) sred[warp] = s;
    __syncthreads();
    if (warp == 0) {
        float v = sred[lane & (TPB / 32 - 1)];
#pragma unroll
        for (int o = (TPB / 64); o > 0; o >>= 1) v += __shfl_xor_sync(0xffffffffu, v, o);
        if (lane == 0) {
            // picked logit: logits[row, target[row]]
            long long tgt;
            if (g_tgt_is64) tgt = reinterpret_cast<const long long*>(target)[row];
            else            tgt = (long long)reinterpret_cast<const int*>(target)[row];
            const float picked = __ldg(logits + base + tgt);
            g_logp[row] = picked - (M + __logf(v));
        }
    }
}

// ---------------------------------------------------------------------------
// Deterministic tree reduction of g_logp -> out[0] = -mean.
// ---------------------------------------------------------------------------
__global__ __launch_bounds__(1024) void final_reduce_kernel(float* __restrict__ out) {
    const int t = threadIdx.x;
    float s = 0.f;
#pragma unroll
    for (int i = 0; i < NROWS / 1024; i++) s += g_logp[t + i * 1024];

    __shared__ float sm[32];
    const int warp = t >> 5, lane = t & 31;
#pragma unroll
    for (int o = 16; o > 0; o >>= 1) s += __shfl_xor_sync(0xffffffffu, s, o);
    if (lane == 0) sm[warp] = s;
    __syncthreads();
    if (warp == 0) {
        float v = sm[lane];
#pragma unroll
        for (int o = 16; o > 0; o >>= 1) v += __shfl_xor_sync(0xffffffffu, v, o);
        if (lane == 0) out[0] = -v * (1.0f / (float)NROWS);
    }
}

extern "C" void kernel_launch(void* const* d_in, const int* in_sizes, int n_in,
                              void* d_out, int out_size) {
    const float* logits = (const float*)d_in[0];
    const float* factor = (const float*)d_in[1];
    const void*  target = d_in[2];

    detect_tgt_kernel<<<1, 1>>>((const int*)target);
    row_kernel<<<NROWS, TPB>>>(logits, factor, target);
    final_reduce_kernel<<<1, 1024>>>((float*)d_out);
}